// round 6
// baseline (speedup 1.0000x reference)
#include <cuda_runtime.h>
#include <math.h>
#include <stdint.h>

#define N_NODES 10000
#define N_EDGES 640000
#define HD      128
#define NHEADS  8
#define TILE    128
#define NTILES  (N_EDGES / TILE)   // 5000
#define EDGE_GRID 148
#define SA_STRIDE 132              // 128 + 4 pad -> conflict-free mma fragment LDS

// scratch (allocation-free rule: __device__ globals)
__device__ float g_Q[N_NODES * HD];
__device__ float g_K[N_NODES * HD];
__device__ float g_V[N_NODES * HD];
__device__ float g_Z[N_NODES * NHEADS];

// edge kernel smem (floats): sE0 + sE1 + sW + sS[2][128*8] + sBe[128]; ints: idx[4][256]
#define SMEM_EDGE  ((3 * TILE * SA_STRIDE + 2 * TILE * NHEADS + 128) * 4 + 4 * 256 * 4)
#define SMEM_PROJ  ((2 * TILE * SA_STRIDE + 128) * 4)

// single extern shared symbol for the whole TU
extern __shared__ char smem_raw[];

__device__ __forceinline__ float cvt_tf32(float x) {
    unsigned u;
    asm("cvt.rna.tf32.f32 %0, %1;" : "=r"(u) : "f"(x));
    return __uint_as_float(u);
}

__device__ __forceinline__ void mma_tf32(float c[4],
                                         unsigned a0, unsigned a1, unsigned a2, unsigned a3,
                                         unsigned b0, unsigned b1) {
    asm volatile(
        "mma.sync.aligned.m16n8k8.row.col.f32.tf32.tf32.f32 "
        "{%0,%1,%2,%3}, {%4,%5,%6,%7}, {%8,%9}, {%0,%1,%2,%3};"
        : "+f"(c[0]), "+f"(c[1]), "+f"(c[2]), "+f"(c[3])
        : "r"(a0), "r"(a1), "r"(a2), "r"(a3), "r"(b0), "r"(b1));
}

// fp32 tile -> smem, tf32-rounded (W operands and k_proj tiles)
template <int NT>
__device__ __forceinline__ void load_tile_tf32(float* dst, const float* __restrict__ src,
                                               int rows, int tid) {
    for (int idx = tid; idx < TILE * 32; idx += NT) {
        int row = idx >> 5, q = idx & 31;
        float4 v = make_float4(0.f, 0.f, 0.f, 0.f);
        if (row < rows) v = ((const float4*)(src + (size_t)row * 128))[q];
        float4 o = make_float4(cvt_tf32(v.x), cvt_tf32(v.y), cvt_tf32(v.z), cvt_tf32(v.w));
        *((float4*)(dst + row * SA_STRIDE + q * 4)) = o;
    }
}

// async raw-fp32 tile prefetch into [128][SA_STRIDE] smem
__device__ __forceinline__ void cp_async_tile(float* sDst, const float* __restrict__ gSrc,
                                              int tid) {
#pragma unroll
    for (int it = 0; it < 8; it++) {
        int idx = tid + it * 512;
        int row = idx >> 5, q = idx & 31;
        unsigned saddr = (unsigned)__cvta_generic_to_shared(sDst + row * SA_STRIDE + q * 4);
        asm volatile("cp.async.cg.shared.global [%0], [%1], 16;\n"
                     :: "r"(saddr), "l"(gSrc + (size_t)row * 128 + q * 4));
    }
}

// ---------------- kernel 0: zero output + z accumulators ----------------
__global__ void k_zero(float* __restrict__ out) {
    int i = blockIdx.x * blockDim.x + threadIdx.x;
    const int n_out4 = N_NODES * HD / 4;
    const int n_z4 = N_NODES * NHEADS / 4;
    float4 z = make_float4(0.f, 0.f, 0.f, 0.f);
    if (i < n_out4) ((float4*)out)[i] = z;
    else if (i < n_out4 + n_z4) ((float4*)g_Z)[i - n_out4] = z;
}

// ---------------- kernel 1: QKV projections -----------------------------
__global__ void __launch_bounds__(512, 1)
k_proj(const float* __restrict__ h,
       const float* __restrict__ Wq, const float* __restrict__ bq,
       const float* __restrict__ Wk, const float* __restrict__ bk,
       const float* __restrict__ Wv, const float* __restrict__ bv) {
    float* smem = (float*)smem_raw;
    float* sA = smem;
    float* sB = sA + TILE * SA_STRIDE;
    float* sBias = sB + TILE * SA_STRIDE;

    const float* W; const float* b; float* outp;
    if (blockIdx.y == 0)      { W = Wq; b = bq; outp = g_Q; }
    else if (blockIdx.y == 1) { W = Wk; b = bk; outp = g_K; }
    else                      { W = Wv; b = bv; outp = g_V; }

    int tid = threadIdx.x;
    int lane = tid & 31, wid = tid >> 5;
    int warp_m = wid & 3, warp_n = wid >> 2;
    int node0 = blockIdx.x * TILE;
    int rows = N_NODES - node0; if (rows > TILE) rows = TILE;

    if (tid < 128) sBias[tid] = b[tid];
    load_tile_tf32<512>(sA, h + (size_t)node0 * 128, rows, tid);
    load_tile_tf32<512>(sB, W, 128, tid);
    __syncthreads();

    float acc[2][4][4];
#pragma unroll
    for (int mt = 0; mt < 2; mt++)
#pragma unroll
        for (int nt = 0; nt < 4; nt++)
#pragma unroll
            for (int i = 0; i < 4; i++) acc[mt][nt][i] = 0.f;

    int gid = lane >> 2, tig = lane & 3;
#pragma unroll
    for (int kk = 0; kk < 16; kk++) {
        int k0 = kk * 8;
        unsigned a[2][4];
#pragma unroll
        for (int mt = 0; mt < 2; mt++) {
            int r = warp_m * 32 + mt * 16 + gid;
            a[mt][0] = __float_as_uint(sA[r * SA_STRIDE + k0 + tig]);
            a[mt][1] = __float_as_uint(sA[(r + 8) * SA_STRIDE + k0 + tig]);
            a[mt][2] = __float_as_uint(sA[r * SA_STRIDE + k0 + tig + 4]);
            a[mt][3] = __float_as_uint(sA[(r + 8) * SA_STRIDE + k0 + tig + 4]);
        }
#pragma unroll
        for (int nt = 0; nt < 4; nt++) {
            int c = warp_n * 32 + nt * 8 + gid;
            unsigned b0 = __float_as_uint(sB[c * SA_STRIDE + k0 + tig]);
            unsigned b1 = __float_as_uint(sB[c * SA_STRIDE + k0 + tig + 4]);
            mma_tf32(acc[0][nt], a[0][0], a[0][1], a[0][2], a[0][3], b0, b1);
            mma_tf32(acc[1][nt], a[1][0], a[1][1], a[1][2], a[1][3], b0, b1);
        }
    }

#pragma unroll
    for (int nt = 0; nt < 4; nt++) {
        int c = warp_n * 32 + nt * 8 + 2 * tig;
        float b0 = sBias[c], b1 = sBias[c + 1];
#pragma unroll
        for (int mt = 0; mt < 2; mt++) {
            int r0 = warp_m * 32 + mt * 16 + gid;
            if (r0 < rows)
                *((float2*)(outp + (size_t)(node0 + r0) * 128 + c)) =
                    make_float2(acc[mt][nt][0] + b0, acc[mt][nt][1] + b1);
            int r1 = r0 + 8;
            if (r1 < rows)
                *((float2*)(outp + (size_t)(node0 + r1) * 128 + c)) =
                    make_float2(acc[mt][nt][2] + b0, acc[mt][nt][3] + b1);
        }
    }
}

// scatter one previous tile: out[dst] += s * V[src], driven from sS/sIdx
__device__ __forceinline__ void scatter_tile(const float* __restrict__ sS,
                                             const int* __restrict__ pSrc,
                                             const int* __restrict__ pDst,
                                             float* __restrict__ out, int tid) {
#pragma unroll
    for (int it = 0; it < 8; it++) {
        int idx = tid + it * 512;
        int row = idx >> 5, q = idx & 31;
        int sN = pSrc[row], dN = pDst[row];
        float sc = sS[row * NHEADS + (q >> 2)];
        float4 v = ((const float4*)(g_V + (size_t)sN * 128))[q];
        float4 r = make_float4(v.x * sc, v.y * sc, v.z * sc, v.w * sc);
        atomicAdd((float4*)(out + (size_t)dN * 128 + q * 4), r);
    }
}

// ---------------- kernel 2: persistent fused edge kernel -----------------
__global__ void __launch_bounds__(512, 1)
k_edge(const float* __restrict__ e, const int* __restrict__ src, const int* __restrict__ dst,
       const float* __restrict__ We, const float* __restrict__ be, float* __restrict__ out) {
    float* smem = (float*)smem_raw;
    float* sE0 = smem;                          // e tile buf 0 (raw fp32)
    float* sE1 = sE0 + TILE * SA_STRIDE;        // e tile buf 1
    float* sW  = sE1 + TILE * SA_STRIDE;        // We (tf32), resident
    float* sS  = sW + TILE * SA_STRIDE;         // [2][128][8] scores, double-buffered
    float* sBe = sS + 2 * TILE * NHEADS;        // [128]
    int* sIdx = (int*)(sBe + 128);              // [4][256]: src|dst per slot

    int tid = threadIdx.x;
    int lane = tid & 31, wid = tid >> 5;
    int warp_m = wid & 3, warp_n = wid >> 2;
    int gid = lane >> 2, tig = lane & 3;
    const int stride = gridDim.x;

    // resident operands
    load_tile_tf32<512>(sW, We, 128, tid);
    if (tid < 128) sBe[tid] = be[tid];

    // prologue: prefetch tiles t0, t0+stride
    int t0 = blockIdx.x;
    if (t0 < NTILES) {
        cp_async_tile(sE0, e + (size_t)t0 * TILE * 128, tid);
        if (tid < 128) {
            sIdx[tid] = src[t0 * TILE + tid];
            sIdx[128 + tid] = dst[t0 * TILE + tid];
        }
    }
    asm volatile("cp.async.commit_group;\n" ::: "memory");
    int t1 = t0 + stride;
    if (t1 < NTILES) {
        cp_async_tile(sE1, e + (size_t)t1 * TILE * 128, tid);
        if (tid < 128) {
            sIdx[256 + tid] = src[t1 * TILE + tid];
            sIdx[256 + 128 + tid] = dst[t1 * TILE + tid];
        }
    }
    asm volatile("cp.async.commit_group;\n" ::: "memory");

    int k = 0;
    int klast = -1;
    for (int t = t0; t < NTILES; t += stride, k++) {
        asm volatile("cp.async.wait_group 1;\n" ::: "memory");
        __syncthreads();   // tile t + idx t visible; prev-iter smem readers done

        float* sE = (k & 1) ? sE1 : sE0;
        const int* sSrc = sIdx + (k & 3) * 256;
        const int* sDst = sSrc + 128;

        // gather K[src]*Q[dst]/sqrt(D) straight into mma-fragment registers;
        // consumed only after the GEMM -> latency hides under tensor work.
        float2 kq[2][2][4];
#pragma unroll
        for (int mt = 0; mt < 2; mt++)
#pragma unroll
            for (int rh = 0; rh < 2; rh++) {
                int r = warp_m * 32 + mt * 16 + rh * 8 + gid;
                const float* Kp = g_K + (size_t)sSrc[r] * 128;
                const float* Qp = g_Q + (size_t)sDst[r] * 128;
#pragma unroll
                for (int nt = 0; nt < 4; nt++) {
                    int c = warp_n * 32 + nt * 8 + 2 * tig;
                    float2 kv = *(const float2*)(Kp + c);
                    float2 qv = *(const float2*)(Qp + c);
                    kq[mt][rh][nt] = make_float2(kv.x * qv.x * 0.25f, kv.y * qv.y * 0.25f);
                }
            }

        float acc[2][4][4];
#pragma unroll
        for (int mt = 0; mt < 2; mt++)
#pragma unroll
            for (int nt = 0; nt < 4; nt++)
#pragma unroll
                for (int i = 0; i < 4; i++) acc[mt][nt][i] = 0.f;

        // GEMM with the previous tile's V-gather + scatter interleaved at kk==7:
        // its L2 traffic overlaps the tensor pipe instead of serializing after it.
#pragma unroll
        for (int kk = 0; kk < 16; kk++) {
            int k0 = kk * 8;
            unsigned a[2][4];
#pragma unroll
            for (int mt = 0; mt < 2; mt++) {
                int r = warp_m * 32 + mt * 16 + gid;
                float v0 = cvt_tf32(sE[r * SA_STRIDE + k0 + tig]);
                float v1 = cvt_tf32(sE[(r + 8) * SA_STRIDE + k0 + tig]);
                float v2 = cvt_tf32(sE[r * SA_STRIDE + k0 + tig + 4]);
                float v3 = cvt_tf32(sE[(r + 8) * SA_STRIDE + k0 + tig + 4]);
                a[mt][0] = __float_as_uint(v0); a[mt][1] = __float_as_uint(v1);
                a[mt][2] = __float_as_uint(v2); a[mt][3] = __float_as_uint(v3);
            }
#pragma unroll
            for (int nt = 0; nt < 4; nt++) {
                int c = warp_n * 32 + nt * 8 + gid;
                unsigned b0 = __float_as_uint(sW[c * SA_STRIDE + k0 + tig]);
                unsigned b1 = __float_as_uint(sW[c * SA_STRIDE + k0 + tig + 4]);
                mma_tf32(acc[0][nt], a[0][0], a[0][1], a[0][2], a[0][3], b0, b1);
                mma_tf32(acc[1][nt], a[1][0], a[1][1], a[1][2], a[1][3], b0, b1);
            }
            if (kk == 7 && k > 0) {
                int kp = k - 1;
                scatter_tile(sS + (kp & 1) * (TILE * NHEADS),
                             sIdx + (kp & 3) * 256, sIdx + (kp & 3) * 256 + 128, out, tid);
            }
        }

        // per-head scores: score[e,h] = sum_d KQ * (E + be)
        float part[2][2][2];
#pragma unroll
        for (int mt = 0; mt < 2; mt++)
#pragma unroll
            for (int rh = 0; rh < 2; rh++)
#pragma unroll
                for (int hg = 0; hg < 2; hg++) part[mt][rh][hg] = 0.f;

#pragma unroll
        for (int nt = 0; nt < 4; nt++) {
            int hg = nt >> 1;
            int c = warp_n * 32 + nt * 8 + 2 * tig;
            float b0 = sBe[c], b1 = sBe[c + 1];
#pragma unroll
            for (int mt = 0; mt < 2; mt++) {
                part[mt][0][hg] += (acc[mt][nt][0] + b0) * kq[mt][0][nt].x
                                 + (acc[mt][nt][1] + b1) * kq[mt][0][nt].y;
                part[mt][1][hg] += (acc[mt][nt][2] + b0) * kq[mt][1][nt].x
                                 + (acc[mt][nt][3] + b1) * kq[mt][1][nt].y;
            }
        }

        float* sSk = sS + (k & 1) * (TILE * NHEADS);
#pragma unroll
        for (int mt = 0; mt < 2; mt++)
#pragma unroll
            for (int rh = 0; rh < 2; rh++)
#pragma unroll
                for (int hg = 0; hg < 2; hg++) {
                    float p = part[mt][rh][hg];
                    p += __shfl_xor_sync(0xffffffffu, p, 1);
                    p += __shfl_xor_sync(0xffffffffu, p, 2);
                    if (tig == 0) {
                        int row = warp_m * 32 + mt * 16 + rh * 8 + gid;
                        int head = warp_n * 2 + hg;
                        float sv = expf(fminf(fmaxf(p, -5.f), 5.f));
                        sSk[row * NHEADS + head] = sv;
                        atomicAdd(&g_Z[(size_t)sDst[row] * NHEADS + head], sv);
                    }
                }
        __syncthreads();   // sS published; sE GEMM reads complete

        // prefetch tile t+2*stride into the buffer just freed
        int t2 = t + 2 * stride;
        if (t2 < NTILES) {
            cp_async_tile(sE, e + (size_t)t2 * TILE * 128, tid);
            if (tid < 128) {
                int* d = sIdx + ((k + 2) & 3) * 256;
                d[tid] = src[t2 * TILE + tid];
                d[128 + tid] = dst[t2 * TILE + tid];
            }
        }
        asm volatile("cp.async.commit_group;\n" ::: "memory");
        klast = k;
    }

    // tail: scatter the final tile
    if (klast >= 0) {
        scatter_tile(sS + (klast & 1) * (TILE * NHEADS),
                     sIdx + (klast & 3) * 256, sIdx + (klast & 3) * 256 + 128, out, tid);
    }
}

// ---------------- kernel 3: normalize -----------------------------------
__global__ void k_final(float* __restrict__ out) {
    int i = blockIdx.x * blockDim.x + threadIdx.x;  // float4 index
    if (i >= N_NODES * HD / 4) return;
    int node = i >> 5;
    int head = (i & 31) >> 2;
    float z = 1.0f / (g_Z[node * NHEADS + head] + 1e-6f);
    float4 v = ((float4*)out)[i];
    v.x *= z; v.y *= z; v.z *= z; v.w *= z;
    ((float4*)out)[i] = v;
}

// ---------------- launcher ------------------------------------------------
extern "C" void kernel_launch(void* const* d_in, const int* in_sizes, int n_in,
                              void* d_out, int out_size) {
    (void)in_sizes; (void)n_in; (void)out_size;
    const float* h  = (const float*)d_in[0];
    const float* e  = (const float*)d_in[1];
    const int*   src = (const int*)d_in[2];
    const int*   dst = (const int*)d_in[3];
    const float* Wq = (const float*)d_in[4];
    const float* bq = (const float*)d_in[5];
    const float* Wk = (const float*)d_in[6];
    const float* bk = (const float*)d_in[7];
    const float* We = (const float*)d_in[8];
    const float* be = (const float*)d_in[9];
    const float* Wv = (const float*)d_in[10];
    const float* bv = (const float*)d_in[11];
    float* out = (float*)d_out;

    cudaFuncSetAttribute(k_proj, cudaFuncAttributeMaxDynamicSharedMemorySize, SMEM_PROJ);
    cudaFuncSetAttribute(k_edge, cudaFuncAttributeMaxDynamicSharedMemorySize, SMEM_EDGE);

    k_zero<<<(N_NODES * HD / 4 + N_NODES * NHEADS / 4 + 255) / 256, 256>>>(out);
    k_proj<<<dim3((N_NODES + TILE - 1) / TILE, 3), 512, SMEM_PROJ>>>(h, Wq, bq, Wk, bk, Wv, bv);
    k_edge<<<EDGE_GRID, 512, SMEM_EDGE>>>(e, src, dst, We, be, out);
    k_final<<<(N_NODES * HD / 4 + 255) / 256, 256>>>(out);
}

// round 7
// speedup vs baseline: 1.1773x; 1.1773x over previous
#include <cuda_runtime.h>
#include <math.h>
#include <stdint.h>

#define N_NODES 10000
#define N_EDGES 640000
#define HD      128
#define NHEADS  8
#define TILE    128                 // k_proj tile
#define TILE_M  64                  // k_edge tile (per half-pipeline)
#define NTILES64 (N_EDGES / TILE_M) // 10000
#define EDGE_GRID 148
#define SA_STRIDE 132               // 128 + 4 pad -> conflict-free mma fragment LDS

// scratch (allocation-free rule: __device__ globals)
__device__ float g_Q[N_NODES * HD];
__device__ float g_K[N_NODES * HD];
__device__ float g_V[N_NODES * HD];
__device__ float g_Z[N_NODES * NHEADS];

// edge smem (floats): sW[128][132] + 4 e-bufs[64][132] + sS[2][64*8] + sBe[128]; ints: idx[2][4][128]
#define SMEM_EDGE ((128 * SA_STRIDE + 4 * TILE_M * SA_STRIDE + 2 * TILE_M * NHEADS + 128) * 4 \
                   + 2 * 4 * 128 * 4)
#define SMEM_PROJ ((2 * TILE * SA_STRIDE + 128) * 4)

// single extern shared symbol for the whole TU
extern __shared__ char smem_raw[];

__device__ __forceinline__ float cvt_tf32(float x) {
    unsigned u;
    asm("cvt.rna.tf32.f32 %0, %1;" : "=r"(u) : "f"(x));
    return __uint_as_float(u);
}

__device__ __forceinline__ void mma_tf32(float c[4],
                                         unsigned a0, unsigned a1, unsigned a2, unsigned a3,
                                         unsigned b0, unsigned b1) {
    asm volatile(
        "mma.sync.aligned.m16n8k8.row.col.f32.tf32.tf32.f32 "
        "{%0,%1,%2,%3}, {%4,%5,%6,%7}, {%8,%9}, {%0,%1,%2,%3};"
        : "+f"(c[0]), "+f"(c[1]), "+f"(c[2]), "+f"(c[3])
        : "r"(a0), "r"(a1), "r"(a2), "r"(a3), "r"(b0), "r"(b1));
}

// fp32 tile -> smem, tf32-rounded (W operands and k_proj tiles)
template <int NT>
__device__ __forceinline__ void load_tile_tf32(float* dst, const float* __restrict__ src,
                                               int rows, int tid) {
    for (int idx = tid; idx < TILE * 32; idx += NT) {
        int row = idx >> 5, q = idx & 31;
        float4 v = make_float4(0.f, 0.f, 0.f, 0.f);
        if (row < rows) v = ((const float4*)(src + (size_t)row * 128))[q];
        float4 o = make_float4(cvt_tf32(v.x), cvt_tf32(v.y), cvt_tf32(v.z), cvt_tf32(v.w));
        *((float4*)(dst + row * SA_STRIDE + q * 4)) = o;
    }
}

// async raw-fp32 64x128 tile prefetch into [64][SA_STRIDE] smem, 256 threads
__device__ __forceinline__ void cp_async_tile64(float* sDst, const float* __restrict__ gSrc,
                                                int htid) {
#pragma unroll
    for (int it = 0; it < 8; it++) {
        int idx = htid + it * 256;         // 2048 16B-chunks
        int row = idx >> 5, q = idx & 31;
        unsigned saddr = (unsigned)__cvta_generic_to_shared(sDst + row * SA_STRIDE + q * 4);
        asm volatile("cp.async.cg.shared.global [%0], [%1], 16;\n"
                     :: "r"(saddr), "l"(gSrc + (size_t)row * 128 + q * 4));
    }
}

__device__ __forceinline__ void bar_half(int half) {
    asm volatile("bar.sync %0, 256;" :: "r"(half + 1) : "memory");
}

// ---------------- kernel 0: zero output + z accumulators ----------------
__global__ void k_zero(float* __restrict__ out) {
    int i = blockIdx.x * blockDim.x + threadIdx.x;
    const int n_out4 = N_NODES * HD / 4;
    const int n_z4 = N_NODES * NHEADS / 4;
    float4 z = make_float4(0.f, 0.f, 0.f, 0.f);
    if (i < n_out4) ((float4*)out)[i] = z;
    else if (i < n_out4 + n_z4) ((float4*)g_Z)[i - n_out4] = z;
}

// ---------------- kernel 1: QKV projections -----------------------------
__global__ void __launch_bounds__(512, 1)
k_proj(const float* __restrict__ h,
       const float* __restrict__ Wq, const float* __restrict__ bq,
       const float* __restrict__ Wk, const float* __restrict__ bk,
       const float* __restrict__ Wv, const float* __restrict__ bv) {
    float* smem = (float*)smem_raw;
    float* sA = smem;
    float* sB = sA + TILE * SA_STRIDE;
    float* sBias = sB + TILE * SA_STRIDE;

    const float* W; const float* b; float* outp;
    if (blockIdx.y == 0)      { W = Wq; b = bq; outp = g_Q; }
    else if (blockIdx.y == 1) { W = Wk; b = bk; outp = g_K; }
    else                      { W = Wv; b = bv; outp = g_V; }

    int tid = threadIdx.x;
    int lane = tid & 31, wid = tid >> 5;
    int warp_m = wid & 3, warp_n = wid >> 2;
    int node0 = blockIdx.x * TILE;
    int rows = N_NODES - node0; if (rows > TILE) rows = TILE;

    if (tid < 128) sBias[tid] = b[tid];
    load_tile_tf32<512>(sA, h + (size_t)node0 * 128, rows, tid);
    load_tile_tf32<512>(sB, W, 128, tid);
    __syncthreads();

    float acc[2][4][4];
#pragma unroll
    for (int mt = 0; mt < 2; mt++)
#pragma unroll
        for (int nt = 0; nt < 4; nt++)
#pragma unroll
            for (int i = 0; i < 4; i++) acc[mt][nt][i] = 0.f;

    int gid = lane >> 2, tig = lane & 3;
#pragma unroll
    for (int kk = 0; kk < 16; kk++) {
        int k0 = kk * 8;
        unsigned a[2][4];
#pragma unroll
        for (int mt = 0; mt < 2; mt++) {
            int r = warp_m * 32 + mt * 16 + gid;
            a[mt][0] = __float_as_uint(sA[r * SA_STRIDE + k0 + tig]);
            a[mt][1] = __float_as_uint(sA[(r + 8) * SA_STRIDE + k0 + tig]);
            a[mt][2] = __float_as_uint(sA[r * SA_STRIDE + k0 + tig + 4]);
            a[mt][3] = __float_as_uint(sA[(r + 8) * SA_STRIDE + k0 + tig + 4]);
        }
#pragma unroll
        for (int nt = 0; nt < 4; nt++) {
            int c = warp_n * 32 + nt * 8 + gid;
            unsigned b0 = __float_as_uint(sB[c * SA_STRIDE + k0 + tig]);
            unsigned b1 = __float_as_uint(sB[c * SA_STRIDE + k0 + tig + 4]);
            mma_tf32(acc[0][nt], a[0][0], a[0][1], a[0][2], a[0][3], b0, b1);
            mma_tf32(acc[1][nt], a[1][0], a[1][1], a[1][2], a[1][3], b0, b1);
        }
    }

#pragma unroll
    for (int nt = 0; nt < 4; nt++) {
        int c = warp_n * 32 + nt * 8 + 2 * tig;
        float b0 = sBias[c], b1 = sBias[c + 1];
#pragma unroll
        for (int mt = 0; mt < 2; mt++) {
            int r0 = warp_m * 32 + mt * 16 + gid;
            if (r0 < rows)
                *((float2*)(outp + (size_t)(node0 + r0) * 128 + c)) =
                    make_float2(acc[mt][nt][0] + b0, acc[mt][nt][1] + b1);
            int r1 = r0 + 8;
            if (r1 < rows)
                *((float2*)(outp + (size_t)(node0 + r1) * 128 + c)) =
                    make_float2(acc[mt][nt][2] + b0, acc[mt][nt][3] + b1);
        }
    }
}

// ---------------- kernel 2: persistent dual-pipeline edge kernel ---------
// 512 threads = two independent 256-thread halves, each on its own stream of
// 64-edge tiles with private e double-buffer / idx / scores and named barriers.
__global__ void __launch_bounds__(512, 1)
k_edge(const float* __restrict__ e, const int* __restrict__ src, const int* __restrict__ dst,
       const float* __restrict__ We, const float* __restrict__ be, float* __restrict__ out) {
    float* smem = (float*)smem_raw;
    float* sW  = smem;                             // [128][132] tf32, shared
    float* sEb = sW + 128 * SA_STRIDE;             // 4 bufs [64][132]
    float* sSb = sEb + 4 * TILE_M * SA_STRIDE;     // [2][64*8]
    float* sBe = sSb + 2 * TILE_M * NHEADS;        // [128]
    int* sIdxB = (int*)(sBe + 128);                // [2][4][128] (64 src + 64 dst)

    int tid = threadIdx.x;
    int half = tid >> 8, htid = tid & 255;
    int lane = tid & 31, hwid = htid >> 5;         // 0..7
    int warp_m = hwid & 1, warp_n = hwid >> 1;     // M: 2x32 rows, N: 4x32 cols
    int gid = lane >> 2, tig = lane & 3;

    // shared resident operands
    load_tile_tf32<512>(sW, We, 128, tid);
    if (tid < 128) sBe[tid] = be[tid];
    __syncthreads();   // last block-wide sync; halves independent below

    float* hE = sEb + half * 2 * TILE_M * SA_STRIDE;   // this half's 2 bufs
    float* hS = sSb + half * TILE_M * NHEADS;          // [64][8]
    int* hIdx = sIdxB + half * 4 * 128;                // 4 slots x (64 src + 64 dst)

    const int stride = gridDim.x * 2;
    const int p0 = blockIdx.x * 2 + half;

    // prologue: prefetch tiles p0 (buf0), p0+stride (buf1)
    if (p0 < NTILES64) {
        cp_async_tile64(hE, e + (size_t)p0 * TILE_M * 128, htid);
        if (htid < 64) {
            hIdx[htid] = src[p0 * TILE_M + htid];
            hIdx[64 + htid] = dst[p0 * TILE_M + htid];
        }
    }
    asm volatile("cp.async.commit_group;\n" ::: "memory");
    if (p0 + stride < NTILES64) {
        cp_async_tile64(hE + TILE_M * SA_STRIDE, e + (size_t)(p0 + stride) * TILE_M * 128, htid);
        if (htid < 64) {
            hIdx[128 + htid] = src[(p0 + stride) * TILE_M + htid];
            hIdx[128 + 64 + htid] = dst[(p0 + stride) * TILE_M + htid];
        }
    }
    asm volatile("cp.async.commit_group;\n" ::: "memory");

    int k = 0;
    for (int t = p0; t < NTILES64; t += stride, k++) {
        asm volatile("cp.async.wait_group 1;\n" ::: "memory");
        bar_half(half);   // tile t + idx visible to this half; prev readers done

        float* sE = hE + (k & 1) * TILE_M * SA_STRIDE;
        const int* sSrc = hIdx + (k & 3) * 128;
        const int* sDst = sSrc + 64;

        // gather K[src]*Q[dst]/sqrt(D) into mma-fragment registers
        float2 kq[2][2][4];
#pragma unroll
        for (int mt = 0; mt < 2; mt++)
#pragma unroll
            for (int rh = 0; rh < 2; rh++) {
                int r = warp_m * 32 + mt * 16 + rh * 8 + gid;
                const float* Kp = g_K + (size_t)sSrc[r] * 128;
                const float* Qp = g_Q + (size_t)sDst[r] * 128;
#pragma unroll
                for (int nt = 0; nt < 4; nt++) {
                    int c = warp_n * 32 + nt * 8 + 2 * tig;
                    float2 kv = *(const float2*)(Kp + c);
                    float2 qv = *(const float2*)(Qp + c);
                    kq[mt][rh][nt] = make_float2(kv.x * qv.x * 0.25f, kv.y * qv.y * 0.25f);
                }
            }

        float acc[2][4][4];
#pragma unroll
        for (int mt = 0; mt < 2; mt++)
#pragma unroll
            for (int nt = 0; nt < 4; nt++)
#pragma unroll
                for (int i = 0; i < 4; i++) acc[mt][nt][i] = 0.f;

        // 64x128x128 GEMM: E_e = e_tile @ We^T (A cvt in regs)
#pragma unroll
        for (int kk = 0; kk < 16; kk++) {
            int k0 = kk * 8;
            unsigned a[2][4];
#pragma unroll
            for (int mt = 0; mt < 2; mt++) {
                int r = warp_m * 32 + mt * 16 + gid;
                float v0 = cvt_tf32(sE[r * SA_STRIDE + k0 + tig]);
                float v1 = cvt_tf32(sE[(r + 8) * SA_STRIDE + k0 + tig]);
                float v2 = cvt_tf32(sE[r * SA_STRIDE + k0 + tig + 4]);
                float v3 = cvt_tf32(sE[(r + 8) * SA_STRIDE + k0 + tig + 4]);
                a[mt][0] = __float_as_uint(v0); a[mt][1] = __float_as_uint(v1);
                a[mt][2] = __float_as_uint(v2); a[mt][3] = __float_as_uint(v3);
            }
#pragma unroll
            for (int nt = 0; nt < 4; nt++) {
                int c = warp_n * 32 + nt * 8 + gid;
                unsigned b0 = __float_as_uint(sW[c * SA_STRIDE + k0 + tig]);
                unsigned b1 = __float_as_uint(sW[c * SA_STRIDE + k0 + tig + 4]);
                mma_tf32(acc[0][nt], a[0][0], a[0][1], a[0][2], a[0][3], b0, b1);
                mma_tf32(acc[1][nt], a[1][0], a[1][1], a[1][2], a[1][3], b0, b1);
            }
        }

        // per-head scores: score[e,h] = sum_d KQ * (E + be)
        float part[2][2][2];
#pragma unroll
        for (int mt = 0; mt < 2; mt++)
#pragma unroll
            for (int rh = 0; rh < 2; rh++)
#pragma unroll
                for (int hg = 0; hg < 2; hg++) part[mt][rh][hg] = 0.f;

#pragma unroll
        for (int nt = 0; nt < 4; nt++) {
            int hg = nt >> 1;
            int c = warp_n * 32 + nt * 8 + 2 * tig;
            float b0 = sBe[c], b1 = sBe[c + 1];
#pragma unroll
            for (int mt = 0; mt < 2; mt++) {
                part[mt][0][hg] += (acc[mt][nt][0] + b0) * kq[mt][0][nt].x
                                 + (acc[mt][nt][1] + b1) * kq[mt][0][nt].y;
                part[mt][1][hg] += (acc[mt][nt][2] + b0) * kq[mt][1][nt].x
                                 + (acc[mt][nt][3] + b1) * kq[mt][1][nt].y;
            }
        }

#pragma unroll
        for (int mt = 0; mt < 2; mt++)
#pragma unroll
            for (int rh = 0; rh < 2; rh++)
#pragma unroll
                for (int hg = 0; hg < 2; hg++) {
                    float p = part[mt][rh][hg];
                    p += __shfl_xor_sync(0xffffffffu, p, 1);
                    p += __shfl_xor_sync(0xffffffffu, p, 2);
                    if (tig == 0) {
                        int row = warp_m * 32 + mt * 16 + rh * 8 + gid;
                        int head = warp_n * 2 + hg;
                        float sv = expf(fminf(fmaxf(p, -5.f), 5.f));
                        hS[row * NHEADS + head] = sv;
                        atomicAdd(&g_Z[(size_t)sDst[row] * NHEADS + head], sv);
                    }
                }
        bar_half(half);   // hS published; sE GEMM reads complete

        // prefetch tile t+2*stride into the buffer just freed
        int t2 = t + 2 * stride;
        if (t2 < NTILES64) {
            cp_async_tile64(sE, e + (size_t)t2 * TILE_M * 128, htid);
            if (htid < 64) {
                int* d = hIdx + ((k + 2) & 3) * 128;
                d[htid] = src[t2 * TILE_M + htid];
                d[64 + htid] = dst[t2 * TILE_M + htid];
            }
        }
        asm volatile("cp.async.commit_group;\n" ::: "memory");

        // scatter: out[dst] += s * V[src]  (overlaps the cp.async just issued)
#pragma unroll
        for (int it = 0; it < 8; it++) {
            int idx = htid + it * 256;
            int row = idx >> 5, q = idx & 31;
            int sN = sSrc[row], dN = sDst[row];
            float sc = hS[row * NHEADS + (q >> 2)];
            float4 v = ((const float4*)(g_V + (size_t)sN * 128))[q];
            float4 r = make_float4(v.x * sc, v.y * sc, v.z * sc, v.w * sc);
            atomicAdd((float4*)(out + (size_t)dN * 128 + q * 4), r);
        }
    }
}

// ---------------- kernel 3: normalize -----------------------------------
__global__ void k_final(float* __restrict__ out) {
    int i = blockIdx.x * blockDim.x + threadIdx.x;  // float4 index
    if (i >= N_NODES * HD / 4) return;
    int node = i >> 5;
    int head = (i & 31) >> 2;
    float z = 1.0f / (g_Z[node * NHEADS + head] + 1e-6f);
    float4 v = ((float4*)out)[i];
    v.x *= z; v.y *= z; v.z *= z; v.w *= z;
    ((float4*)out)[i] = v;
}

// ---------------- launcher ------------------------------------------------
extern "C" void kernel_launch(void* const* d_in, const int* in_sizes, int n_in,
                              void* d_out, int out_size) {
    (void)in_sizes; (void)n_in; (void)out_size;
    const float* h  = (const float*)d_in[0];
    const float* e  = (const float*)d_in[1];
    const int*   src = (const int*)d_in[2];
    const int*   dst = (const int*)d_in[3];
    const float* Wq = (const float*)d_in[4];
    const float* bq = (const float*)d_in[5];
    const float* Wk = (const float*)d_in[6];
    const float* bk = (const float*)d_in[7];
    const float* We = (const float*)d_in[8];
    const float* be = (const float*)d_in[9];
    const float* Wv = (const float*)d_in[10];
    const float* bv = (const float*)d_in[11];
    float* out = (float*)d_out;

    cudaFuncSetAttribute(k_proj, cudaFuncAttributeMaxDynamicSharedMemorySize, SMEM_PROJ);
    cudaFuncSetAttribute(k_edge, cudaFuncAttributeMaxDynamicSharedMemorySize, SMEM_EDGE);

    k_zero<<<(N_NODES * HD / 4 + N_NODES * NHEADS / 4 + 255) / 256, 256>>>(out);
    k_proj<<<dim3((N_NODES + TILE - 1) / TILE, 3), 512, SMEM_PROJ>>>(h, Wq, bq, Wk, bk, Wv, bv);
    k_edge<<<EDGE_GRID, 512, SMEM_EDGE>>>(e, src, dst, We, be, out);
    k_final<<<(N_NODES * HD / 4 + 255) / 256, 256>>>(out);
}

// round 8
// speedup vs baseline: 1.2016x; 1.0206x over previous
#include <cuda_runtime.h>
#include <math.h>
#include <stdint.h>

#define N_NODES 10000
#define N_EDGES 640000
#define HD      128
#define NHEADS  8
#define TILE    128                 // k_proj tile
#define TILE_M  32                  // k_edge tile (per quarter-pipeline)
#define NTILES32 (N_EDGES / TILE_M) // 20000
#define EDGE_GRID 148
#define SA_STRIDE 132               // 128 + 4 pad -> conflict-free mma fragment LDS

// scratch (allocation-free rule: __device__ globals)
__device__ float g_Q[N_NODES * HD];
__device__ float g_K[N_NODES * HD];
__device__ float g_V[N_NODES * HD];
__device__ float g_Z[N_NODES * NHEADS];

// edge smem (floats): sW[128][132] + 8 e-bufs[32][132] + sS[4][32*8] + sBe[128]; ints: idx[4][4][64]
#define SMEM_EDGE ((128 * SA_STRIDE + 8 * TILE_M * SA_STRIDE + 4 * TILE_M * NHEADS + 128) * 4 \
                   + 4 * 4 * 64 * 4)
#define SMEM_PROJ ((2 * TILE * SA_STRIDE + 128) * 4)

// single extern shared symbol for the whole TU
extern __shared__ char smem_raw[];

__device__ __forceinline__ float cvt_tf32(float x) {
    unsigned u;
    asm("cvt.rna.tf32.f32 %0, %1;" : "=r"(u) : "f"(x));
    return __uint_as_float(u);
}

__device__ __forceinline__ void mma_tf32(float c[4],
                                         unsigned a0, unsigned a1, unsigned a2, unsigned a3,
                                         unsigned b0, unsigned b1) {
    asm volatile(
        "mma.sync.aligned.m16n8k8.row.col.f32.tf32.tf32.f32 "
        "{%0,%1,%2,%3}, {%4,%5,%6,%7}, {%8,%9}, {%0,%1,%2,%3};"
        : "+f"(c[0]), "+f"(c[1]), "+f"(c[2]), "+f"(c[3])
        : "r"(a0), "r"(a1), "r"(a2), "r"(a3), "r"(b0), "r"(b1));
}

// fp32 tile -> smem, tf32-rounded (W operands and k_proj tiles)
template <int NT>
__device__ __forceinline__ void load_tile_tf32(float* dst, const float* __restrict__ src,
                                               int rows, int tid) {
    for (int idx = tid; idx < TILE * 32; idx += NT) {
        int row = idx >> 5, q = idx & 31;
        float4 v = make_float4(0.f, 0.f, 0.f, 0.f);
        if (row < rows) v = ((const float4*)(src + (size_t)row * 128))[q];
        float4 o = make_float4(cvt_tf32(v.x), cvt_tf32(v.y), cvt_tf32(v.z), cvt_tf32(v.w));
        *((float4*)(dst + row * SA_STRIDE + q * 4)) = o;
    }
}

// async raw-fp32 32x128 tile prefetch into [32][SA_STRIDE] smem, 128 threads
__device__ __forceinline__ void cp_async_tile32(float* sDst, const float* __restrict__ gSrc,
                                                int qtid) {
#pragma unroll
    for (int it = 0; it < 8; it++) {
        int idx = qtid + it * 128;         // 1024 16B-chunks
        int row = idx >> 5, q = idx & 31;
        unsigned saddr = (unsigned)__cvta_generic_to_shared(sDst + row * SA_STRIDE + q * 4);
        asm volatile("cp.async.cg.shared.global [%0], [%1], 16;\n"
                     :: "r"(saddr), "l"(gSrc + (size_t)row * 128 + q * 4));
    }
}

__device__ __forceinline__ void bar_q(int q) {
    asm volatile("bar.sync %0, 128;" :: "r"(q + 1) : "memory");
}

// ---------------- kernel 0: zero output + z accumulators ----------------
__global__ void k_zero(float* __restrict__ out) {
    int i = blockIdx.x * blockDim.x + threadIdx.x;
    const int n_out4 = N_NODES * HD / 4;
    const int n_z4 = N_NODES * NHEADS / 4;
    float4 z = make_float4(0.f, 0.f, 0.f, 0.f);
    if (i < n_out4) ((float4*)out)[i] = z;
    else if (i < n_out4 + n_z4) ((float4*)g_Z)[i - n_out4] = z;
}

// ---------------- kernel 1: QKV projections -----------------------------
__global__ void __launch_bounds__(512, 1)
k_proj(const float* __restrict__ h,
       const float* __restrict__ Wq, const float* __restrict__ bq,
       const float* __restrict__ Wk, const float* __restrict__ bk,
       const float* __restrict__ Wv, const float* __restrict__ bv) {
    float* smem = (float*)smem_raw;
    float* sA = smem;
    float* sB = sA + TILE * SA_STRIDE;
    float* sBias = sB + TILE * SA_STRIDE;

    const float* W; const float* b; float* outp;
    if (blockIdx.y == 0)      { W = Wq; b = bq; outp = g_Q; }
    else if (blockIdx.y == 1) { W = Wk; b = bk; outp = g_K; }
    else                      { W = Wv; b = bv; outp = g_V; }

    int tid = threadIdx.x;
    int lane = tid & 31, wid = tid >> 5;
    int warp_m = wid & 3, warp_n = wid >> 2;
    int node0 = blockIdx.x * TILE;
    int rows = N_NODES - node0; if (rows > TILE) rows = TILE;

    if (tid < 128) sBias[tid] = b[tid];
    load_tile_tf32<512>(sA, h + (size_t)node0 * 128, rows, tid);
    load_tile_tf32<512>(sB, W, 128, tid);
    __syncthreads();

    float acc[2][4][4];
#pragma unroll
    for (int mt = 0; mt < 2; mt++)
#pragma unroll
        for (int nt = 0; nt < 4; nt++)
#pragma unroll
            for (int i = 0; i < 4; i++) acc[mt][nt][i] = 0.f;

    int gid = lane >> 2, tig = lane & 3;
#pragma unroll
    for (int kk = 0; kk < 16; kk++) {
        int k0 = kk * 8;
        unsigned a[2][4];
#pragma unroll
        for (int mt = 0; mt < 2; mt++) {
            int r = warp_m * 32 + mt * 16 + gid;
            a[mt][0] = __float_as_uint(sA[r * SA_STRIDE + k0 + tig]);
            a[mt][1] = __float_as_uint(sA[(r + 8) * SA_STRIDE + k0 + tig]);
            a[mt][2] = __float_as_uint(sA[r * SA_STRIDE + k0 + tig + 4]);
            a[mt][3] = __float_as_uint(sA[(r + 8) * SA_STRIDE + k0 + tig + 4]);
        }
#pragma unroll
        for (int nt = 0; nt < 4; nt++) {
            int c = warp_n * 32 + nt * 8 + gid;
            unsigned b0 = __float_as_uint(sB[c * SA_STRIDE + k0 + tig]);
            unsigned b1 = __float_as_uint(sB[c * SA_STRIDE + k0 + tig + 4]);
            mma_tf32(acc[0][nt], a[0][0], a[0][1], a[0][2], a[0][3], b0, b1);
            mma_tf32(acc[1][nt], a[1][0], a[1][1], a[1][2], a[1][3], b0, b1);
        }
    }

#pragma unroll
    for (int nt = 0; nt < 4; nt++) {
        int c = warp_n * 32 + nt * 8 + 2 * tig;
        float b0 = sBias[c], b1 = sBias[c + 1];
#pragma unroll
        for (int mt = 0; mt < 2; mt++) {
            int r0 = warp_m * 32 + mt * 16 + gid;
            if (r0 < rows)
                *((float2*)(outp + (size_t)(node0 + r0) * 128 + c)) =
                    make_float2(acc[mt][nt][0] + b0, acc[mt][nt][1] + b1);
            int r1 = r0 + 8;
            if (r1 < rows)
                *((float2*)(outp + (size_t)(node0 + r1) * 128 + c)) =
                    make_float2(acc[mt][nt][2] + b0, acc[mt][nt][3] + b1);
        }
    }
}

// ---------------- kernel 2: persistent quad-pipeline edge kernel ---------
// 512 threads = four independent 128-thread quarters, each on its own stream
// of 32-edge tiles with private e double-buffer / idx / scores and named
// barriers. W + be shared (loaded once).
__global__ void __launch_bounds__(512, 1)
k_edge(const float* __restrict__ e, const int* __restrict__ src, const int* __restrict__ dst,
       const float* __restrict__ We, const float* __restrict__ be, float* __restrict__ out) {
    float* smem = (float*)smem_raw;
    float* sW  = smem;                             // [128][132] tf32, shared
    float* sEb = sW + 128 * SA_STRIDE;             // 8 bufs [32][132]
    float* sSb = sEb + 8 * TILE_M * SA_STRIDE;     // [4][32*8]
    float* sBe = sSb + 4 * TILE_M * NHEADS;        // [128]
    int* sIdxB = (int*)(sBe + 128);                // [4][4][64] (32 src + 32 dst)

    int tid = threadIdx.x;
    int qtr = tid >> 7, qtid = tid & 127;
    int lane = tid & 31;
    int warp_n = qtid >> 5;                        // 0..3: 32-col group
    int gid = lane >> 2, tig = lane & 3;

    // shared resident operands
    load_tile_tf32<512>(sW, We, 128, tid);
    if (tid < 128) sBe[tid] = be[tid];
    __syncthreads();   // last block-wide sync; quarters independent below

    float* hE = sEb + qtr * 2 * TILE_M * SA_STRIDE;   // this quarter's 2 bufs
    float* hS = sSb + qtr * TILE_M * NHEADS;          // [32][8]
    int* hIdx = sIdxB + qtr * 4 * 64;                 // 4 slots x (32 src + 32 dst)

    const int stride = gridDim.x * 4;
    const int p0 = blockIdx.x * 4 + qtr;

    // prologue: prefetch tiles p0 (buf0), p0+stride (buf1)
    if (p0 < NTILES32) {
        cp_async_tile32(hE, e + (size_t)p0 * TILE_M * 128, qtid);
        if (qtid < 32) {
            hIdx[qtid] = src[p0 * TILE_M + qtid];
            hIdx[32 + qtid] = dst[p0 * TILE_M + qtid];
        }
    }
    asm volatile("cp.async.commit_group;\n" ::: "memory");
    if (p0 + stride < NTILES32) {
        cp_async_tile32(hE + TILE_M * SA_STRIDE, e + (size_t)(p0 + stride) * TILE_M * 128, qtid);
        if (qtid < 32) {
            hIdx[64 + qtid] = src[(p0 + stride) * TILE_M + qtid];
            hIdx[64 + 32 + qtid] = dst[(p0 + stride) * TILE_M + qtid];
        }
    }
    asm volatile("cp.async.commit_group;\n" ::: "memory");

    int k = 0;
    for (int t = p0; t < NTILES32; t += stride, k++) {
        asm volatile("cp.async.wait_group 1;\n" ::: "memory");
        bar_q(qtr);   // tile t + idx visible to this quarter; prev readers done

        float* sE = hE + (k & 1) * TILE_M * SA_STRIDE;
        const int* sSrc = hIdx + (k & 3) * 64;
        const int* sDst = sSrc + 32;

        // gather K[src]*Q[dst]/sqrt(D) into mma-fragment registers
        float2 kq[2][2][4];
#pragma unroll
        for (int mt = 0; mt < 2; mt++)
#pragma unroll
            for (int rh = 0; rh < 2; rh++) {
                int r = mt * 16 + rh * 8 + gid;
                const float* Kp = g_K + (size_t)sSrc[r] * 128;
                const float* Qp = g_Q + (size_t)sDst[r] * 128;
#pragma unroll
                for (int nt = 0; nt < 4; nt++) {
                    int c = warp_n * 32 + nt * 8 + 2 * tig;
                    float2 kv = *(const float2*)(Kp + c);
                    float2 qv = *(const float2*)(Qp + c);
                    kq[mt][rh][nt] = make_float2(kv.x * qv.x * 0.25f, kv.y * qv.y * 0.25f);
                }
            }

        float acc[2][4][4];
#pragma unroll
        for (int mt = 0; mt < 2; mt++)
#pragma unroll
            for (int nt = 0; nt < 4; nt++)
#pragma unroll
                for (int i = 0; i < 4; i++) acc[mt][nt][i] = 0.f;

        // 32x128x128 GEMM: E_e = e_tile @ We^T (A cvt in regs)
#pragma unroll
        for (int kk = 0; kk < 16; kk++) {
            int k0 = kk * 8;
            unsigned a[2][4];
#pragma unroll
            for (int mt = 0; mt < 2; mt++) {
                int r = mt * 16 + gid;
                float v0 = cvt_tf32(sE[r * SA_STRIDE + k0 + tig]);
                float v1 = cvt_tf32(sE[(r + 8) * SA_STRIDE + k0 + tig]);
                float v2 = cvt_tf32(sE[r * SA_STRIDE + k0 + tig + 4]);
                float v3 = cvt_tf32(sE[(r + 8) * SA_STRIDE + k0 + tig + 4]);
                a[mt][0] = __float_as_uint(v0); a[mt][1] = __float_as_uint(v1);
                a[mt][2] = __float_as_uint(v2); a[mt][3] = __float_as_uint(v3);
            }
#pragma unroll
            for (int nt = 0; nt < 4; nt++) {
                int c = warp_n * 32 + nt * 8 + gid;
                unsigned b0 = __float_as_uint(sW[c * SA_STRIDE + k0 + tig]);
                unsigned b1 = __float_as_uint(sW[c * SA_STRIDE + k0 + tig + 4]);
                mma_tf32(acc[0][nt], a[0][0], a[0][1], a[0][2], a[0][3], b0, b1);
                mma_tf32(acc[1][nt], a[1][0], a[1][1], a[1][2], a[1][3], b0, b1);
            }
        }

        // per-head scores: score[e,h] = sum_d KQ * (E + be)
        float part[2][2][2];
#pragma unroll
        for (int mt = 0; mt < 2; mt++)
#pragma unroll
            for (int rh = 0; rh < 2; rh++)
#pragma unroll
                for (int hg = 0; hg < 2; hg++) part[mt][rh][hg] = 0.f;

#pragma unroll
        for (int nt = 0; nt < 4; nt++) {
            int hg = nt >> 1;
            int c = warp_n * 32 + nt * 8 + 2 * tig;
            float b0 = sBe[c], b1 = sBe[c + 1];
#pragma unroll
            for (int mt = 0; mt < 2; mt++) {
                part[mt][0][hg] += (acc[mt][nt][0] + b0) * kq[mt][0][nt].x
                                 + (acc[mt][nt][1] + b1) * kq[mt][0][nt].y;
                part[mt][1][hg] += (acc[mt][nt][2] + b0) * kq[mt][1][nt].x
                                 + (acc[mt][nt][3] + b1) * kq[mt][1][nt].y;
            }
        }

#pragma unroll
        for (int mt = 0; mt < 2; mt++)
#pragma unroll
            for (int rh = 0; rh < 2; rh++)
#pragma unroll
                for (int hg = 0; hg < 2; hg++) {
                    float p = part[mt][rh][hg];
                    p += __shfl_xor_sync(0xffffffffu, p, 1);
                    p += __shfl_xor_sync(0xffffffffu, p, 2);
                    if (tig == 0) {
                        int row = mt * 16 + rh * 8 + gid;
                        int head = warp_n * 2 + hg;
                        float sv = expf(fminf(fmaxf(p, -5.f), 5.f));
                        hS[row * NHEADS + head] = sv;
                        atomicAdd(&g_Z[(size_t)sDst[row] * NHEADS + head], sv);
                    }
                }
        bar_q(qtr);   // hS published; sE GEMM reads complete

        // prefetch tile t+2*stride into the buffer just freed
        int t2 = t + 2 * stride;
        if (t2 < NTILES32) {
            cp_async_tile32(sE, e + (size_t)t2 * TILE_M * 128, qtid);
            if (qtid < 32) {
                int* d = hIdx + ((k + 2) & 3) * 64;
                d[qtid] = src[t2 * TILE_M + qtid];
                d[32 + qtid] = dst[t2 * TILE_M + qtid];
            }
        }
        asm volatile("cp.async.commit_group;\n" ::: "memory");

        // scatter: out[dst] += s * V[src]  (overlaps the cp.async just issued)
#pragma unroll
        for (int it = 0; it < 8; it++) {
            int idx = qtid + it * 128;
            int row = idx >> 5, q = idx & 31;
            int sN = sSrc[row], dN = sDst[row];
            float sc = hS[row * NHEADS + (q >> 2)];
            float4 v = ((const float4*)(g_V + (size_t)sN * 128))[q];
            float4 r = make_float4(v.x * sc, v.y * sc, v.z * sc, v.w * sc);
            atomicAdd((float4*)(out + (size_t)dN * 128 + q * 4), r);
        }
    }
}

// ---------------- kernel 3: normalize -----------------------------------
__global__ void k_final(float* __restrict__ out) {
    int i = blockIdx.x * blockDim.x + threadIdx.x;  // float4 index
    if (i >= N_NODES * HD / 4) return;
    int node = i >> 5;
    int head = (i & 31) >> 2;
    float z = 1.0f / (g_Z[node * NHEADS + head] + 1e-6f);
    float4 v = ((float4*)out)[i];
    v.x *= z; v.y *= z; v.z *= z; v.w *= z;
    ((float4*)out)[i] = v;
}

// ---------------- launcher ------------------------------------------------
extern "C" void kernel_launch(void* const* d_in, const int* in_sizes, int n_in,
                              void* d_out, int out_size) {
    (void)in_sizes; (void)n_in; (void)out_size;
    const float* h  = (const float*)d_in[0];
    const float* e  = (const float*)d_in[1];
    const int*   src = (const int*)d_in[2];
    const int*   dst = (const int*)d_in[3];
    const float* Wq = (const float*)d_in[4];
    const float* bq = (const float*)d_in[5];
    const float* Wk = (const float*)d_in[6];
    const float* bk = (const float*)d_in[7];
    const float* We = (const float*)d_in[8];
    const float* be = (const float*)d_in[9];
    const float* Wv = (const float*)d_in[10];
    const float* bv = (const float*)d_in[11];
    float* out = (float*)d_out;

    cudaFuncSetAttribute(k_proj, cudaFuncAttributeMaxDynamicSharedMemorySize, SMEM_PROJ);
    cudaFuncSetAttribute(k_edge, cudaFuncAttributeMaxDynamicSharedMemorySize, SMEM_EDGE);

    k_zero<<<(N_NODES * HD / 4 + N_NODES * NHEADS / 4 + 255) / 256, 256>>>(out);
    k_proj<<<dim3((N_NODES + TILE - 1) / TILE, 3), 512, SMEM_PROJ>>>(h, Wq, bq, Wk, bk, Wv, bv);
    k_edge<<<EDGE_GRID, 512, SMEM_EDGE>>>(e, src, dst, We, be, out);
    k_final<<<(N_NODES * HD / 4 + 255) / 256, 256>>>(out);
}

// round 9
// speedup vs baseline: 1.2272x; 1.0213x over previous
#include <cuda_runtime.h>
#include <math.h>
#include <stdint.h>

#define N_NODES 10000
#define N_EDGES 640000
#define HD      128
#define NHEADS  8
#define TILE    128                 // k_proj tile
#define TILE_M  32                  // k_edge tile (per quarter-pipeline)
#define NTILES32 (N_EDGES / TILE_M) // 20000
#define EDGE_GRID 148
#define SA_STRIDE 132               // scalar-LDS tiles (e bufs, k_proj)
#define SW_STRIDE 136               // permuted W: stride ≡ 8 (mod 32) -> LDS.64 conflict-free

// scratch (allocation-free rule: __device__ globals)
__device__ float g_Q[N_NODES * HD];
__device__ float g_K[N_NODES * HD];
__device__ float g_V[N_NODES * HD];
__device__ float g_Z[N_NODES * NHEADS];

// edge smem (floats): sWp[128][136] + 8 e-bufs[32][132] + sS[4][32*8] + sBe[128]; ints: idx[4][4][64]
#define SMEM_EDGE ((128 * SW_STRIDE + 8 * TILE_M * SA_STRIDE + 4 * TILE_M * NHEADS + 128) * 4 \
                   + 4 * 4 * 64 * 4)
#define SMEM_PROJ ((2 * TILE * SA_STRIDE + 128) * 4)

// single extern shared symbol for the whole TU
extern __shared__ char smem_raw[];

__device__ __forceinline__ float cvt_tf32(float x) {
    unsigned u;
    asm("cvt.rna.tf32.f32 %0, %1;" : "=r"(u) : "f"(x));
    return __uint_as_float(u);
}

__device__ __forceinline__ void mma_tf32(float c[4],
                                         unsigned a0, unsigned a1, unsigned a2, unsigned a3,
                                         unsigned b0, unsigned b1) {
    asm volatile(
        "mma.sync.aligned.m16n8k8.row.col.f32.tf32.tf32.f32 "
        "{%0,%1,%2,%3}, {%4,%5,%6,%7}, {%8,%9}, {%0,%1,%2,%3};"
        : "+f"(c[0]), "+f"(c[1]), "+f"(c[2]), "+f"(c[3])
        : "r"(a0), "r"(a1), "r"(a2), "r"(a3), "r"(b0), "r"(b1));
}

// fp32 tile -> smem, tf32-rounded (k_proj operands)
template <int NT>
__device__ __forceinline__ void load_tile_tf32(float* dst, const float* __restrict__ src,
                                               int rows, int tid) {
    for (int idx = tid; idx < TILE * 32; idx += NT) {
        int row = idx >> 5, q = idx & 31;
        float4 v = make_float4(0.f, 0.f, 0.f, 0.f);
        if (row < rows) v = ((const float4*)(src + (size_t)row * 128))[q];
        float4 o = make_float4(cvt_tf32(v.x), cvt_tf32(v.y), cvt_tf32(v.z), cvt_tf32(v.w));
        *((float4*)(dst + row * SA_STRIDE + q * 4)) = o;
    }
}

// async raw-fp32 32x128 tile prefetch into [32][SA_STRIDE] smem, 128 threads
__device__ __forceinline__ void cp_async_tile32(float* sDst, const float* __restrict__ gSrc,
                                                int qtid) {
#pragma unroll
    for (int it = 0; it < 8; it++) {
        int idx = qtid + it * 128;         // 1024 16B-chunks
        int row = idx >> 5, q = idx & 31;
        unsigned saddr = (unsigned)__cvta_generic_to_shared(sDst + row * SA_STRIDE + q * 4);
        asm volatile("cp.async.cg.shared.global [%0], [%1], 16;\n"
                     :: "r"(saddr), "l"(gSrc + (size_t)row * 128 + q * 4));
    }
}

__device__ __forceinline__ void bar_q(int q) {
    asm volatile("bar.sync %0, 128;" :: "r"(q + 1) : "memory");
}

// ---------------- kernel 0: zero output + z accumulators ----------------
__global__ void k_zero(float* __restrict__ out) {
    int i = blockIdx.x * blockDim.x + threadIdx.x;
    const int n_out4 = N_NODES * HD / 4;
    const int n_z4 = N_NODES * NHEADS / 4;
    float4 z = make_float4(0.f, 0.f, 0.f, 0.f);
    if (i < n_out4) ((float4*)out)[i] = z;
    else if (i < n_out4 + n_z4) ((float4*)g_Z)[i - n_out4] = z;
}

// ---------------- kernel 1: QKV projections -----------------------------
__global__ void __launch_bounds__(512, 1)
k_proj(const float* __restrict__ h,
       const float* __restrict__ Wq, const float* __restrict__ bq,
       const float* __restrict__ Wk, const float* __restrict__ bk,
       const float* __restrict__ Wv, const float* __restrict__ bv) {
    float* smem = (float*)smem_raw;
    float* sA = smem;
    float* sB = sA + TILE * SA_STRIDE;
    float* sBias = sB + TILE * SA_STRIDE;

    const float* W; const float* b; float* outp;
    if (blockIdx.y == 0)      { W = Wq; b = bq; outp = g_Q; }
    else if (blockIdx.y == 1) { W = Wk; b = bk; outp = g_K; }
    else                      { W = Wv; b = bv; outp = g_V; }

    int tid = threadIdx.x;
    int lane = tid & 31, wid = tid >> 5;
    int warp_m = wid & 3, warp_n = wid >> 2;
    int node0 = blockIdx.x * TILE;
    int rows = N_NODES - node0; if (rows > TILE) rows = TILE;

    if (tid < 128) sBias[tid] = b[tid];
    load_tile_tf32<512>(sA, h + (size_t)node0 * 128, rows, tid);
    load_tile_tf32<512>(sB, W, 128, tid);
    __syncthreads();

    float acc[2][4][4];
#pragma unroll
    for (int mt = 0; mt < 2; mt++)
#pragma unroll
        for (int nt = 0; nt < 4; nt++)
#pragma unroll
            for (int i = 0; i < 4; i++) acc[mt][nt][i] = 0.f;

    int gid = lane >> 2, tig = lane & 3;
#pragma unroll
    for (int kk = 0; kk < 16; kk++) {
        int k0 = kk * 8;
        unsigned a[2][4];
#pragma unroll
        for (int mt = 0; mt < 2; mt++) {
            int r = warp_m * 32 + mt * 16 + gid;
            a[mt][0] = __float_as_uint(sA[r * SA_STRIDE + k0 + tig]);
            a[mt][1] = __float_as_uint(sA[(r + 8) * SA_STRIDE + k0 + tig]);
            a[mt][2] = __float_as_uint(sA[r * SA_STRIDE + k0 + tig + 4]);
            a[mt][3] = __float_as_uint(sA[(r + 8) * SA_STRIDE + k0 + tig + 4]);
        }
#pragma unroll
        for (int nt = 0; nt < 4; nt++) {
            int c = warp_n * 32 + nt * 8 + gid;
            unsigned b0 = __float_as_uint(sB[c * SA_STRIDE + k0 + tig]);
            unsigned b1 = __float_as_uint(sB[c * SA_STRIDE + k0 + tig + 4]);
            mma_tf32(acc[0][nt], a[0][0], a[0][1], a[0][2], a[0][3], b0, b1);
            mma_tf32(acc[1][nt], a[1][0], a[1][1], a[1][2], a[1][3], b0, b1);
        }
    }

#pragma unroll
    for (int nt = 0; nt < 4; nt++) {
        int c = warp_n * 32 + nt * 8 + 2 * tig;
        float b0 = sBias[c], b1 = sBias[c + 1];
#pragma unroll
        for (int mt = 0; mt < 2; mt++) {
            int r0 = warp_m * 32 + mt * 16 + gid;
            if (r0 < rows)
                *((float2*)(outp + (size_t)(node0 + r0) * 128 + c)) =
                    make_float2(acc[mt][nt][0] + b0, acc[mt][nt][1] + b1);
            int r1 = r0 + 8;
            if (r1 < rows)
                *((float2*)(outp + (size_t)(node0 + r1) * 128 + c)) =
                    make_float2(acc[mt][nt][2] + b0, acc[mt][nt][3] + b1);
        }
    }
}

// ---------------- kernel 2: persistent quad-pipeline edge kernel ---------
// 512 threads = four independent 128-thread quarters on private 32-edge tile
// streams (named barriers). W permuted for LDS.64 B-fragments; A fragments
// feed the tf32 mma raw (HW reads bits[31:13] -> truncation).
__global__ void __launch_bounds__(512, 1)
k_edge(const float* __restrict__ e, const int* __restrict__ src, const int* __restrict__ dst,
       const float* __restrict__ We, const float* __restrict__ be, float* __restrict__ out) {
    float* smem = (float*)smem_raw;
    float* sWp = smem;                             // [128][136] tf32, pair-permuted
    float* sEb = sWp + 128 * SW_STRIDE;            // 8 bufs [32][132]
    float* sSb = sEb + 8 * TILE_M * SA_STRIDE;     // [4][32*8]
    float* sBe = sSb + 4 * TILE_M * NHEADS;        // [128]
    int* sIdxB = (int*)(sBe + 128);                // [4][4][64] (32 src + 32 dst)

    int tid = threadIdx.x;
    int qtr = tid >> 7, qtid = tid & 127;
    int lane = tid & 31;
    int warp_n = qtid >> 5;                        // 0..3: 32-col group
    int gid = lane >> 2, tig = lane & 3;

    // shared resident W with pair-permuted columns: cols (k, k+4) adjacent
    for (int idx = tid; idx < 128 * 128; idx += 512) {
        int row = idx >> 7, col = idx & 127;
        int pc = (col & ~7) | ((col & 3) << 1) | ((col >> 2) & 1);
        sWp[row * SW_STRIDE + pc] = cvt_tf32(We[idx]);
    }
    if (tid < 128) sBe[tid] = be[tid];
    __syncthreads();   // last block-wide sync; quarters independent below

    float* hE = sEb + qtr * 2 * TILE_M * SA_STRIDE;   // this quarter's 2 bufs
    float* hS = sSb + qtr * TILE_M * NHEADS;          // [32][8]
    int* hIdx = sIdxB + qtr * 4 * 64;                 // 4 slots x (32 src + 32 dst)

    const int stride = gridDim.x * 4;
    const int p0 = blockIdx.x * 4 + qtr;

    // prologue: prefetch tiles p0 (buf0), p0+stride (buf1)
    if (p0 < NTILES32) {
        cp_async_tile32(hE, e + (size_t)p0 * TILE_M * 128, qtid);
        if (qtid < 32) {
            hIdx[qtid] = src[p0 * TILE_M + qtid];
            hIdx[32 + qtid] = dst[p0 * TILE_M + qtid];
        }
    }
    asm volatile("cp.async.commit_group;\n" ::: "memory");
    if (p0 + stride < NTILES32) {
        cp_async_tile32(hE + TILE_M * SA_STRIDE, e + (size_t)(p0 + stride) * TILE_M * 128, qtid);
        if (qtid < 32) {
            hIdx[64 + qtid] = src[(p0 + stride) * TILE_M + qtid];
            hIdx[64 + 32 + qtid] = dst[(p0 + stride) * TILE_M + qtid];
        }
    }
    asm volatile("cp.async.commit_group;\n" ::: "memory");

    int k = 0;
    for (int t = p0; t < NTILES32; t += stride, k++) {
        asm volatile("cp.async.wait_group 1;\n" ::: "memory");
        bar_q(qtr);   // tile t + idx visible to this quarter; prev readers done

        float* sE = hE + (k & 1) * TILE_M * SA_STRIDE;
        const int* sSrc = hIdx + (k & 3) * 64;
        const int* sDst = sSrc + 32;

        // gather K[src]*Q[dst]/sqrt(D) into mma-fragment registers
        float2 kq[2][2][4];
#pragma unroll
        for (int mt = 0; mt < 2; mt++)
#pragma unroll
            for (int rh = 0; rh < 2; rh++) {
                int r = mt * 16 + rh * 8 + gid;
                const float* Kp = g_K + (size_t)sSrc[r] * 128;
                const float* Qp = g_Q + (size_t)sDst[r] * 128;
#pragma unroll
                for (int nt = 0; nt < 4; nt++) {
                    int c = warp_n * 32 + nt * 8 + 2 * tig;
                    float2 kv = *(const float2*)(Kp + c);
                    float2 qv = *(const float2*)(Qp + c);
                    kq[mt][rh][nt] = make_float2(kv.x * qv.x * 0.25f, kv.y * qv.y * 0.25f);
                }
            }

        float acc[2][4][4];
#pragma unroll
        for (int mt = 0; mt < 2; mt++)
#pragma unroll
            for (int nt = 0; nt < 4; nt++)
#pragma unroll
                for (int i = 0; i < 4; i++) acc[mt][nt][i] = 0.f;

        // 32x128x128 GEMM: E_e = e_tile @ We^T
        // A fed raw (tf32 HW truncation); B via LDS.64 from permuted W.
#pragma unroll
        for (int kk = 0; kk < 16; kk++) {
            int k0 = kk * 8;
            unsigned a[2][4];
#pragma unroll
            for (int mt = 0; mt < 2; mt++) {
                int r = mt * 16 + gid;
                a[mt][0] = __float_as_uint(sE[r * SA_STRIDE + k0 + tig]);
                a[mt][1] = __float_as_uint(sE[(r + 8) * SA_STRIDE + k0 + tig]);
                a[mt][2] = __float_as_uint(sE[r * SA_STRIDE + k0 + tig + 4]);
                a[mt][3] = __float_as_uint(sE[(r + 8) * SA_STRIDE + k0 + tig + 4]);
            }
#pragma unroll
            for (int nt = 0; nt < 4; nt++) {
                int c = warp_n * 32 + nt * 8 + gid;
                float2 bv = *(const float2*)(sWp + c * SW_STRIDE + k0 + 2 * tig);
                unsigned b0 = __float_as_uint(bv.x);
                unsigned b1 = __float_as_uint(bv.y);
                mma_tf32(acc[0][nt], a[0][0], a[0][1], a[0][2], a[0][3], b0, b1);
                mma_tf32(acc[1][nt], a[1][0], a[1][1], a[1][2], a[1][3], b0, b1);
            }
        }

        // per-head scores: score[e,h] = sum_d KQ * (E + be)
        float part[2][2][2];
#pragma unroll
        for (int mt = 0; mt < 2; mt++)
#pragma unroll
            for (int rh = 0; rh < 2; rh++)
#pragma unroll
                for (int hg = 0; hg < 2; hg++) part[mt][rh][hg] = 0.f;

#pragma unroll
        for (int nt = 0; nt < 4; nt++) {
            int hg = nt >> 1;
            int c = warp_n * 32 + nt * 8 + 2 * tig;
            float b0 = sBe[c], b1 = sBe[c + 1];
#pragma unroll
            for (int mt = 0; mt < 2; mt++) {
                part[mt][0][hg] += (acc[mt][nt][0] + b0) * kq[mt][0][nt].x
                                 + (acc[mt][nt][1] + b1) * kq[mt][0][nt].y;
                part[mt][1][hg] += (acc[mt][nt][2] + b0) * kq[mt][1][nt].x
                                 + (acc[mt][nt][3] + b1) * kq[mt][1][nt].y;
            }
        }

#pragma unroll
        for (int mt = 0; mt < 2; mt++)
#pragma unroll
            for (int rh = 0; rh < 2; rh++)
#pragma unroll
                for (int hg = 0; hg < 2; hg++) {
                    float p = part[mt][rh][hg];
                    p += __shfl_xor_sync(0xffffffffu, p, 1);
                    p += __shfl_xor_sync(0xffffffffu, p, 2);
                    if (tig == 0) {
                        int row = mt * 16 + rh * 8 + gid;
                        int head = warp_n * 2 + hg;
                        float sv = __expf(fminf(fmaxf(p, -5.f), 5.f));
                        hS[row * NHEADS + head] = sv;
                        atomicAdd(&g_Z[(size_t)sDst[row] * NHEADS + head], sv);
                    }
                }
        bar_q(qtr);   // hS published; sE GEMM reads complete

        // prefetch tile t+2*stride into the buffer just freed
        int t2 = t + 2 * stride;
        if (t2 < NTILES32) {
            cp_async_tile32(sE, e + (size_t)t2 * TILE_M * 128, qtid);
            if (qtid < 32) {
                int* d = hIdx + ((k + 2) & 3) * 64;
                d[qtid] = src[t2 * TILE_M + qtid];
                d[32 + qtid] = dst[t2 * TILE_M + qtid];
            }
        }
        asm volatile("cp.async.commit_group;\n" ::: "memory");

        // scatter: out[dst] += s * V[src]  (overlaps the cp.async just issued)
#pragma unroll
        for (int it = 0; it < 8; it++) {
            int idx = qtid + it * 128;
            int row = idx >> 5, q = idx & 31;
            int sN = sSrc[row], dN = sDst[row];
            float sc = hS[row * NHEADS + (q >> 2)];
            float4 v = ((const float4*)(g_V + (size_t)sN * 128))[q];
            float4 r = make_float4(v.x * sc, v.y * sc, v.z * sc, v.w * sc);
            atomicAdd((float4*)(out + (size_t)dN * 128 + q * 4), r);
        }
    }
}

// ---------------- kernel 3: normalize -----------------------------------
__global__ void k_final(float* __restrict__ out) {
    int i = blockIdx.x * blockDim.x + threadIdx.x;  // float4 index
    if (i >= N_NODES * HD / 4) return;
    int node = i >> 5;
    int head = (i & 31) >> 2;
    float z = 1.0f / (g_Z[node * NHEADS + head] + 1e-6f);
    float4 v = ((float4*)out)[i];
    v.x *= z; v.y *= z; v.z *= z; v.w *= z;
    ((float4*)out)[i] = v;
}

// ---------------- launcher ------------------------------------------------
extern "C" void kernel_launch(void* const* d_in, const int* in_sizes, int n_in,
                              void* d_out, int out_size) {
    (void)in_sizes; (void)n_in; (void)out_size;
    const float* h  = (const float*)d_in[0];
    const float* e  = (const float*)d_in[1];
    const int*   src = (const int*)d_in[2];
    const int*   dst = (const int*)d_in[3];
    const float* Wq = (const float*)d_in[4];
    const float* bq = (const float*)d_in[5];
    const float* Wk = (const float*)d_in[6];
    const float* bk = (const float*)d_in[7];
    const float* We = (const float*)d_in[8];
    const float* be = (const float*)d_in[9];
    const float* Wv = (const float*)d_in[10];
    const float* bv = (const float*)d_in[11];
    float* out = (float*)d_out;

    cudaFuncSetAttribute(k_proj, cudaFuncAttributeMaxDynamicSharedMemorySize, SMEM_PROJ);
    cudaFuncSetAttribute(k_edge, cudaFuncAttributeMaxDynamicSharedMemorySize, SMEM_EDGE);

    k_zero<<<(N_NODES * HD / 4 + N_NODES * NHEADS / 4 + 255) / 256, 256>>>(out);
    k_proj<<<dim3((N_NODES + TILE - 1) / TILE, 3), 512, SMEM_PROJ>>>(h, Wq, bq, Wk, bk, Wv, bv);
    k_edge<<<EDGE_GRID, 512, SMEM_EDGE>>>(e, src, dst, We, be, out);
    k_final<<<(N_NODES * HD / 4 + 255) / 256, 256>>>(out);
}